// round 2
// baseline (speedup 1.0000x reference)
#include <cuda_runtime.h>

// LocalConvolutionMix: per-pixel local conv, 3x3(pad1) + 5x5(pad2) branches.
// x:  [4, 256, 56, 56] f32
// w1: [4, 1, 32, 9,  56, 56]
// w2: [4, 1, 32, 25, 56, 56]
// out:[4, 2, 1, 256, 56, 56]
//
// Block = (28, 8): each thread computes 2 adjacent W pixels for 8 channel
// groups (two passes of 4) and both branches. Vectorized LDS.64/LDG.64/STG.64.

#define N_   4
#define C_   256
#define H_   56
#define W_   56
#define WC_  32
#define G_   8
#define TH_  8
#define TW_  28        // threads along W (2 pixels each)
#define HW_  (H_*W_)

__global__ __launch_bounds__(TW_*TH_, 5)
void localconv_mix_kernel(const float* __restrict__ x,
                          const float* __restrict__ w1,
                          const float* __restrict__ w2,
                          float* __restrict__ out)
{
    // x tile: 8 groups, 12 rows (8 + 4 halo), 60 cols (56 + 4 halo)
    __shared__ __align__(16) float xs[G_][TH_ + 4][W_ + 4];

    const int tx = threadIdx.x;          // 0..27
    const int ty = threadIdx.y;          // 0..7
    const int h0 = blockIdx.x * TH_;
    const int v  = blockIdx.y;           // 0..31
    const int n  = blockIdx.z;           // 0..3

    // ---- stage x tile (zero-padded halo) ----
    const int tid = ty * TW_ + tx;                      // 0..223
    const int nthreads = TW_ * TH_;                     // 224
    const int tile_elems = G_ * (TH_ + 4) * (W_ + 4);   // 5760
    float* xs_flat = &xs[0][0][0];

    #pragma unroll 1
    for (int e = tid; e < tile_elems; e += nthreads) {
        int g   = e / ((TH_ + 4) * (W_ + 4));
        int rem = e - g * ((TH_ + 4) * (W_ + 4));
        int r   = rem / (W_ + 4);
        int col = rem - r * (W_ + 4);
        int hh = h0 - 2 + r;
        int ww = col - 2;
        float val = 0.0f;
        if (hh >= 0 && hh < H_ && ww >= 0 && ww < W_) {
            int c = g * WC_ + v;
            val = x[(((size_t)n * C_ + c) * H_ + hh) * W_ + ww];
        }
        xs_flat[e] = val;
    }
    __syncthreads();

    const int h  = h0 + ty;
    const int w0 = 2 * tx;                 // first of the 2 pixels
    const size_t pix = (size_t)h * W_ + w0;

    const float* w2p = w2 + ((size_t)(n * WC_ + v) * 25) * HW_ + pix;
    const float* w1p = w1 + ((size_t)(n * WC_ + v) * 9)  * HW_ + pix;

    // two passes over channel groups: g in [gbase, gbase+4)
    #pragma unroll 1
    for (int pass = 0; pass < 2; pass++) {
        const int gbase = pass * 4;

        float2 a1[4], a2[4];
        #pragma unroll
        for (int g = 0; g < 4; g++) {
            a1[g] = make_float2(0.f, 0.f);
            a2[g] = make_float2(0.f, 0.f);
        }

        #pragma unroll
        for (int ki = 0; ki < 5; ki++) {
            // row weights for both pixels: float2 (pix, pix+1 contiguous)
            float2 w2r[5];
            #pragma unroll
            for (int kj = 0; kj < 5; kj++)
                w2r[kj] = __ldg((const float2*)(w2p + (size_t)(ki * 5 + kj) * HW_));

            const bool mid = (ki >= 1 && ki <= 3);
            float2 w1r[3];
            if (mid) {
                #pragma unroll
                for (int kj = 0; kj < 3; kj++)
                    w1r[kj] = __ldg((const float2*)(w1p + (size_t)((ki - 1) * 3 + kj) * HW_));
            }

            #pragma unroll
            for (int g = 0; g < 4; g++) {
                const float* row = &xs[gbase + g][ty + ki][w0];
                const float2 x01 = *(const float2*)(row + 0);
                const float2 x23 = *(const float2*)(row + 2);
                const float2 x45 = *(const float2*)(row + 4);
                const float win[6] = {x01.x, x01.y, x23.x, x23.y, x45.x, x45.y};

                #pragma unroll
                for (int kj = 0; kj < 5; kj++) {
                    a2[g].x = fmaf(w2r[kj].x, win[kj],     a2[g].x);
                    a2[g].y = fmaf(w2r[kj].y, win[kj + 1], a2[g].y);
                }
                if (mid) {
                    #pragma unroll
                    for (int kj = 1; kj <= 3; kj++) {
                        a1[g].x = fmaf(w1r[kj - 1].x, win[kj],     a1[g].x);
                        a1[g].y = fmaf(w1r[kj - 1].y, win[kj + 1], a1[g].y);
                    }
                }
            }
        }

        #pragma unroll
        for (int g = 0; g < 4; g++) {
            const int c = (gbase + g) * WC_ + v;
            *(float2*)&out[(((size_t)n * 2 + 0) * C_ + c) * HW_ + pix] = a1[g];
            *(float2*)&out[(((size_t)n * 2 + 1) * C_ + c) * HW_ + pix] = a2[g];
        }
    }
}

extern "C" void kernel_launch(void* const* d_in, const int* in_sizes, int n_in,
                              void* d_out, int out_size)
{
    const float* x  = (const float*)d_in[0];
    const float* w1 = (const float*)d_in[1];
    const float* w2 = (const float*)d_in[2];
    float* out = (float*)d_out;

    dim3 block(TW_, TH_);          // 224 threads
    dim3 grid(H_ / TH_, WC_, N_);  // (7, 32, 4) = 896 blocks
    localconv_mix_kernel<<<grid, block>>>(x, w1, w2, out);
}

// round 3
// speedup vs baseline: 2.4216x; 2.4216x over previous
#include <cuda_runtime.h>

// LocalConvolutionMix: per-pixel local conv, 3x3(pad1) + 5x5(pad2) branches.
// x:  [4, 256, 56, 56] f32
// w1: [4, 1, 32, 9,  56, 56]
// w2: [4, 1, 32, 25, 56, 56]
// out:[4, 2, 1, 256, 56, 56]
//
// Block = (28, 8) = 224 threads. Each thread: 2 adjacent W pixels x 4 channel
// groups x 2 branches (16 outputs). Groups split across blockIdx.y (2 halves);
// paired blocks share weight cachelines via L2.

#define N_    4
#define C_    256
#define H_    56
#define W_    56
#define WC_   32
#define GPB_  4          // channel groups per block
#define TH_   8          // rows per block
#define TW_   28         // threads along W (2 px each)
#define HW_   (H_*W_)
#define TCOL_ 64         // padded smem row length

__global__ __launch_bounds__(TW_*TH_, 5)
void localconv_mix_kernel(const float* __restrict__ x,
                          const float* __restrict__ w1,
                          const float* __restrict__ w2,
                          float* __restrict__ out)
{
    // x tile: 4 groups, 12 rows (8 + 4 halo), 64 cols (56 + 4 halo, padded)
    __shared__ __align__(16) float xs[GPB_][TH_ + 4][TCOL_];

    const int tx = threadIdx.x;            // 0..27
    const int ty = threadIdx.y;            // 0..7
    const int h0 = blockIdx.x * TH_;
    const int by = blockIdx.y;             // 0..63: v = by>>1, half = by&1
    const int v     = by >> 1;
    const int gbase = (by & 1) * GPB_;
    const int n  = blockIdx.z;

    // ---- stage x tile (zero-padded halo) ----
    const int tid = ty * TW_ + tx;                      // 0..223
    const int nthreads = TW_ * TH_;                     // 224
    const int tile_elems = GPB_ * (TH_ + 4) * TCOL_;    // 3072
    float* xs_flat = &xs[0][0][0];

    #pragma unroll 1
    for (int e = tid; e < tile_elems; e += nthreads) {
        int g   = e / ((TH_ + 4) * TCOL_);
        int rem = e - g * ((TH_ + 4) * TCOL_);
        int r   = rem / TCOL_;
        int col = rem - r * TCOL_;
        int hh = h0 - 2 + r;
        int ww = col - 2;
        float val = 0.0f;
        if (hh >= 0 && hh < H_ && ww >= 0 && ww < W_) {
            int c = (gbase + g) * WC_ + v;
            val = x[(((size_t)n * C_ + c) * H_ + hh) * W_ + ww];
        }
        xs_flat[e] = val;
    }
    __syncthreads();

    const int h  = h0 + ty;
    const int w0 = 2 * tx;
    const size_t pix = (size_t)h * W_ + w0;

    const float* w2p = w2 + ((size_t)(n * WC_ + v) * 25) * HW_ + pix;
    const float* w1p = w1 + ((size_t)(n * WC_ + v) * 9)  * HW_ + pix;

    float2 a1[GPB_], a2[GPB_];
    #pragma unroll
    for (int g = 0; g < GPB_; g++) {
        a1[g] = make_float2(0.f, 0.f);
        a2[g] = make_float2(0.f, 0.f);
    }

    #pragma unroll
    for (int ki = 0; ki < 5; ki++) {
        // prefetch this row's weights for both pixels (LDG.64, coalesced)
        float2 w2r0 = __ldg((const float2*)(w2p + (size_t)(ki * 5 + 0) * HW_));
        float2 w2r1 = __ldg((const float2*)(w2p + (size_t)(ki * 5 + 1) * HW_));
        float2 w2r2 = __ldg((const float2*)(w2p + (size_t)(ki * 5 + 2) * HW_));
        float2 w2r3 = __ldg((const float2*)(w2p + (size_t)(ki * 5 + 3) * HW_));
        float2 w2r4 = __ldg((const float2*)(w2p + (size_t)(ki * 5 + 4) * HW_));

        const bool mid = (ki >= 1 && ki <= 3);
        float2 w1r0, w1r1, w1r2;
        if (mid) {
            w1r0 = __ldg((const float2*)(w1p + (size_t)((ki - 1) * 3 + 0) * HW_));
            w1r1 = __ldg((const float2*)(w1p + (size_t)((ki - 1) * 3 + 1) * HW_));
            w1r2 = __ldg((const float2*)(w1p + (size_t)((ki - 1) * 3 + 2) * HW_));
        }

        #pragma unroll
        for (int g = 0; g < GPB_; g++) {
            const float* row = &xs[g][ty + ki][w0];
            const float2 p01 = *(const float2*)(row + 0);
            const float2 p23 = *(const float2*)(row + 2);
            const float2 p45 = *(const float2*)(row + 4);
            const float x0 = p01.x, x1 = p01.y, x2 = p23.x,
                        x3 = p23.y, x4 = p45.x, x5 = p45.y;

            a2[g].x = fmaf(w2r0.x, x0, a2[g].x);
            a2[g].y = fmaf(w2r0.y, x1, a2[g].y);
            a2[g].x = fmaf(w2r1.x, x1, a2[g].x);
            a2[g].y = fmaf(w2r1.y, x2, a2[g].y);
            a2[g].x = fmaf(w2r2.x, x2, a2[g].x);
            a2[g].y = fmaf(w2r2.y, x3, a2[g].y);
            a2[g].x = fmaf(w2r3.x, x3, a2[g].x);
            a2[g].y = fmaf(w2r3.y, x4, a2[g].y);
            a2[g].x = fmaf(w2r4.x, x4, a2[g].x);
            a2[g].y = fmaf(w2r4.y, x5, a2[g].y);

            if (mid) {
                a1[g].x = fmaf(w1r0.x, x1, a1[g].x);
                a1[g].y = fmaf(w1r0.y, x2, a1[g].y);
                a1[g].x = fmaf(w1r1.x, x2, a1[g].x);
                a1[g].y = fmaf(w1r1.y, x3, a1[g].y);
                a1[g].x = fmaf(w1r2.x, x3, a1[g].x);
                a1[g].y = fmaf(w1r2.y, x4, a1[g].y);
            }
        }
    }

    #pragma unroll
    for (int g = 0; g < GPB_; g++) {
        const int c = (gbase + g) * WC_ + v;
        *(float2*)&out[(((size_t)n * 2 + 0) * C_ + c) * HW_ + pix] = a1[g];
        *(float2*)&out[(((size_t)n * 2 + 1) * C_ + c) * HW_ + pix] = a2[g];
    }
}

extern "C" void kernel_launch(void* const* d_in, const int* in_sizes, int n_in,
                              void* d_out, int out_size)
{
    const float* x  = (const float*)d_in[0];
    const float* w1 = (const float*)d_in[1];
    const float* w2 = (const float*)d_in[2];
    float* out = (float*)d_out;

    dim3 block(TW_, TH_);           // 224 threads
    dim3 grid(H_ / TH_, WC_ * 2, N_); // (7, 64, 4) = 1792 blocks
    localconv_mix_kernel<<<grid, block>>>(x, w1, w2, out);
}